// round 7
// baseline (speedup 1.0000x reference)
#include <cuda_runtime.h>

// ---------------------------------------------------------------------------
// HBV hydrological model, T=2000, G=4000, NMUL=4, warmup=365, 15-tap routing.
//
//   k1: hbv_kernel     — one thread per (g,m) chain; 2000-step sequential
//                        scan, critical-path-minimized; shfl mean over NMUL;
//                        writes qs[T][G] (32MB scratch).
//   k2: weights_kernel — gamma 15-tap unit hydrograph (normalization cancels
//                        the gammaln/th^aa denominator exactly).
//   k3: conv_kernel    — 15-tap FIR, 2D grid (g-block, t): no div/mod,
//                        coalesced along g.
// ---------------------------------------------------------------------------

#define T_LEN 2000
#define G_LEN 4000
#define NMULC 4
#define WARM  365
#define LENF  15
#define NPHY  12
#define PRM_STRIDE (NPHY * NMULC + 2)   // 50

__device__ float g_qs[(size_t)T_LEN * G_LEN];   // 32 MB scratch
__device__ float g_w[LENF * G_LEN];             // routing weights

__constant__ float c_lb[NPHY] = {1.0f, 50.0f, 0.05f, 0.01f, 0.001f, 0.2f,
                                 0.0f, 0.0f, -2.5f, 0.5f, 0.0f, 0.0f};
__constant__ float c_ub[NPHY] = {6.0f, 1000.0f, 0.9f, 0.5f, 0.2f, 1.0f,
                                 10.0f, 100.0f, 2.5f, 10.0f, 0.1f, 0.2f};

// ---------------------------------------------------------------------------
// Kernel 1: sequential HBV scan, dependency-latency bound. All input-only
// work (rain/snow split, melt/refreeze potentials, PET scaling) is computed
// at prefetch time, one iteration ahead of use, so the recurrent chain per
// step is only: snow-store updates (~24cyc, hidden) and the sm chain
// (MUFU pow ~40cyc + ~30cyc of FMA/FMNMX), giving ~75 cycles/step.
// Block 128 => 125 blocks <= 148 SMs: one warp per SMSP.
// ---------------------------------------------------------------------------
__global__ void __launch_bounds__(128)
hbv_kernel(const float* __restrict__ x, const float* __restrict__ prm)
{
    const int tid = blockIdx.x * 128 + threadIdx.x;
    if (tid >= G_LEN * NMULC) return;
    const int g = tid >> 2;
    const int m = tid & 3;

    // De-normalize the 12 physical parameters for this (g, m).
    const float* pr = prm + (size_t)g * PRM_STRIDE;
    float ph[NPHY];
#pragma unroll
    for (int i = 0; i < NPHY; i++) {
        float raw = pr[i * NMULC + m];
        ph[i] = c_lb[i] + raw * (c_ub[i] - c_lb[i]);
    }
    const float beta  = ph[0], fc   = ph[1], k0  = ph[2], k1 = ph[3];
    const float k2    = ph[4], lp   = ph[5], perc = ph[6], uzl = ph[7];
    const float tt    = ph[8], cfmax = ph[9], cfr = ph[10], cwh = ph[11];

    const float inv_fc   = 1.0f / fc;
    const float inv_lpfc = 1.0f / (lp * fc);
    const float cfrcf    = cfr * cfmax;

    float snowpack = 0.001f, meltwater = 0.001f, sm = 0.001f;
    float suz = 0.001f, slz = 0.001f;

    // ---- prefetch + preprocess forcing for step 0 (input-only work) ----
    const float* x0 = x + (size_t)g * 3;
    float P0 = x0[0], T0 = x0[1], E0 = x0[2];
    float rain  = (T0 >= tt) ? P0 : 0.0f;          // rain
    float snow  = P0 - rain;                       // snow
    float mpot  = fmaxf(cfmax * (T0 - tt), 0.0f);  // melt potential
    float rfpot = fmaxf(cfrcf * (tt - T0), 0.0f);  // refreeze potential
    float PE    = E0;                              // PET
    float PEl   = E0 * inv_lpfc;                   // PET / (lp*fc)

    for (int t = 0; t < T_LEN; t++) {
        // ---- prefetch + preprocess NEXT step's forcing (off-chain) ----
        const int tn = (t + 1 < T_LEN) ? (t + 1) : (T_LEN - 1);
        const float* xn = x + ((size_t)tn * G_LEN + g) * 3;
        const float Pn = xn[0], Tn = xn[1], En = xn[2];
        const float rain_n  = (Tn >= tt) ? Pn : 0.0f;
        const float snow_n  = Pn - rain_n;
        const float mpot_n  = fmaxf(cfmax * (Tn - tt), 0.0f);
        const float rfpot_n = fmaxf(cfrcf * (tt - Tn), 0.0f);
        const float PEl_n   = En * inv_lpfc;

        // ---- sw from previous sm: start the MUFU chain IMMEDIATELY ----
        // sm/fc in (0,1] (sm>=1e-5, sm<=fc by construction): fast path safe.
        // EX2 output is >=0; clamp to 1 matches reference clip.
        float sw = __powf(sm * inv_fc, beta);
        sw = fminf(sw, 1.0f);
        const float omsw = 1.0f - sw;

        // ---- snow routine (runs in parallel with the MUFU chain) ----
        snowpack += snow;
        const float melt = fminf(mpot, snowpack);
        const float mw1  = meltwater + melt;
        const float refreeze = fminf(rfpot, mw1);
        snowpack = snowpack - melt + refreeze;
        const float mw2 = mw1 - refreeze;
        const float tosoil = fmaxf(mw2 - cwh * snowpack, 0.0f);
        meltwater = mw2 - tosoil;

        // ---- soil routine (critical chain) ----
        const float influx   = rain + tosoil;
        const float recharge = influx * sw;
        const float sm1 = fmaf(influx, omsw, sm);       // sm + influx*(1-sw)
        const float excess = fmaxf(sm1 - fc, 0.0f);
        const float sm2 = fminf(sm1, fc);               // == sm1 - excess
        // etact = min(sm2, PE * clip(sm2/(lp*fc),0,1))
        //       = min(min(sm2, PE), PEl * sm2)          (PE >= 0)
        const float etact = fminf(fminf(sm2, PE), PEl * sm2);
        sm = fmaxf(sm2 - etact, 1e-5f);

        // ---- response routine ----
        const float suz1 = suz + recharge + excess;
        const float prc  = fminf(suz1, perc);
        const float suz2 = suz1 - prc;
        const float q0   = k0 * fmaxf(suz2 - uzl, 0.0f);
        const float suz3 = suz2 - q0;
        const float q1   = k1 * suz3;
        suz = suz3 - q1;
        const float slz1 = slz + prc;
        const float q2   = k2 * slz1;
        slz = slz1 - q2;

        // ---- mean over NMUL (4 adjacent lanes); off the state chain ----
        float q = q0 + q1 + q2;
        q += __shfl_xor_sync(0xFFFFFFFFu, q, 1);
        q += __shfl_xor_sync(0xFFFFFFFFu, q, 2);
        if (m == 0)
            g_qs[(size_t)t * G_LEN + g] = q * 0.25f;

        // ---- rotate prefetched forcing ----
        rain = rain_n; snow = snow_n; mpot = mpot_n; rfpot = rfpot_n;
        PE = En; PEl = PEl_n;
    }
}

// ---------------------------------------------------------------------------
// Kernel 2: 15-tap gamma unit hydrograph per grid cell. The normalization by
// w.sum(0) cancels 1/(Gamma(aa)*th^aa) exactly; only tg^(aa-1)*exp(-tg/th)
// matters.
// ---------------------------------------------------------------------------
__global__ void __launch_bounds__(128)
weights_kernel(const float* __restrict__ prm)
{
    const int g = blockIdx.x * 128 + threadIdx.x;
    if (g >= G_LEN) return;
    const float* pr = prm + (size_t)g * PRM_STRIDE;
    const float a = pr[NPHY * NMULC + 0] * 2.9f;   // ROUTE_A in [0, 2.9]
    const float b = pr[NPHY * NMULC + 1] * 6.5f;   // ROUTE_B in [0, 6.5]
    const float aa = fmaxf(a, 0.0f) + 0.1f;
    const float th = fmaxf(b, 0.0f) + 0.5f;
    const float inv_th = 1.0f / th;
    const float am1 = aa - 1.0f;

    float u[LENF];
    float s = 0.0f;
#pragma unroll
    for (int l = 0; l < LENF; l++) {
        const float tg = (float)l + 0.5f;
        const float v = powf(tg, am1) * expf(-tg * inv_th);
        u[l] = v;
        s += v;
    }
    const float inv_s = 1.0f / s;
#pragma unroll
    for (int l = 0; l < LENF; l++)
        g_w[l * G_LEN + g] = u[l] * inv_s;
}

// ---------------------------------------------------------------------------
// Kernel 3: 15-tap FIR over qs. 2D grid: blockIdx.y = output time row,
// (blockIdx.x, threadIdx.x) cover g. No integer div/mod; fully coalesced
// along g. out[t - WARM, g] = sum_l w[l][g] * qs[t-l][g]; all taps in range
// for t >= WARM >= LENF. qs (32MB) is L2-resident across the 15x reuse.
// ---------------------------------------------------------------------------
__global__ void __launch_bounds__(256)
conv_kernel(float* __restrict__ out)
{
    const int g = blockIdx.x * 256 + threadIdx.x;
    if (g >= G_LEN) return;
    const int t = blockIdx.y + WARM;

    float acc = 0.0f;
#pragma unroll
    for (int l = 0; l < LENF; l++)
        acc += g_w[l * G_LEN + g] * g_qs[(size_t)(t - l) * G_LEN + g];

    out[(size_t)blockIdx.y * G_LEN + g] = acc;
}

// ---------------------------------------------------------------------------
extern "C" void kernel_launch(void* const* d_in, const int* in_sizes, int n_in,
                              void* d_out, int out_size)
{
    const float* x_phy = (const float*)d_in[0];   // [2000, 4000, 3]
    const float* prm   = (const float*)d_in[1];   // [1, 4000, 50]
    float* out = (float*)d_out;                   // [1635, 4000, 1]

    const int n_chains = G_LEN * NMULC;           // 16000
    hbv_kernel<<<(n_chains + 127) / 128, 128>>>(x_phy, prm);
    weights_kernel<<<(G_LEN + 127) / 128, 128>>>(prm);
    dim3 cgrid((G_LEN + 255) / 256, T_LEN - WARM);   // (16, 1635)
    conv_kernel<<<cgrid, 256>>>(out);
    (void)in_sizes; (void)n_in; (void)out_size;
}

// round 15
// speedup vs baseline: 3.3649x; 3.3649x over previous
#include <cuda_runtime.h>

// ---------------------------------------------------------------------------
// HBV hydrological model, T=2000, G=4000, NMUL=4, warmup=365, 15-tap routing.
//
// R7 ncu: scan kernel ~1.09ms, occ 6.2%, issue 6.8%, DRAM 1.3% => warp is
// stalled on forcing-load latency (~1000 cyc/step exposed; prefetch depth was
// only 1 step). Fix: depth-16 register-ring software pipeline for the
// forcing loads; loads for t+16 issue at step t (16 x ~70cyc slack > ~1000cyc
// latency; 48 outstanding LDGs < per-warp cap ~55).
// ---------------------------------------------------------------------------

#define T_LEN 2000
#define G_LEN 4000
#define NMULC 4
#define WARM  365
#define LENF  15
#define NPHY  12
#define PRM_STRIDE (NPHY * NMULC + 2)   // 50
#define DEPTH 16                         // prefetch distance (T_LEN % DEPTH == 0)

__device__ float g_qs[(size_t)T_LEN * G_LEN];   // 32 MB scratch
__device__ float g_w[LENF * G_LEN];             // routing weights

__constant__ float c_lb[NPHY] = {1.0f, 50.0f, 0.05f, 0.01f, 0.001f, 0.2f,
                                 0.0f, 0.0f, -2.5f, 0.5f, 0.0f, 0.0f};
__constant__ float c_ub[NPHY] = {6.0f, 1000.0f, 0.9f, 0.5f, 0.2f, 1.0f,
                                 10.0f, 100.0f, 2.5f, 10.0f, 0.1f, 0.2f};

// ---------------------------------------------------------------------------
// Kernel 1: sequential HBV scan with depth-16 load pipelining.
// One thread per (g,m); 4 NMUL lanes adjacent for shfl mean.
// ---------------------------------------------------------------------------
__global__ void __launch_bounds__(128)
hbv_kernel(const float* __restrict__ x, const float* __restrict__ prm)
{
    const int tid = blockIdx.x * 128 + threadIdx.x;
    if (tid >= G_LEN * NMULC) return;
    const int g = tid >> 2;
    const int m = tid & 3;

    // De-normalize the 12 physical parameters for this (g, m).
    const float* pr = prm + (size_t)g * PRM_STRIDE;
    float ph[NPHY];
#pragma unroll
    for (int i = 0; i < NPHY; i++) {
        float raw = pr[i * NMULC + m];
        ph[i] = c_lb[i] + raw * (c_ub[i] - c_lb[i]);
    }
    const float beta  = ph[0], fc   = ph[1], k0  = ph[2], k1 = ph[3];
    const float k2    = ph[4], lp   = ph[5], perc = ph[6], uzl = ph[7];
    const float tt    = ph[8], cfmax = ph[9], cfr = ph[10], cwh = ph[11];

    const float inv_fc   = 1.0f / fc;
    const float inv_lpfc = 1.0f / (lp * fc);
    const float cfrcf    = cfr * cfmax;

    float snowpack = 0.001f, meltwater = 0.001f, sm = 0.001f;
    float suz = 0.001f, slz = 0.001f;

    // ---- register ring: forcing for steps t .. t+DEPTH-1 ----
    float bP[DEPTH], bT[DEPTH], bE[DEPTH];
#pragma unroll
    for (int d = 0; d < DEPTH; d++) {
        const float* xp = x + ((size_t)d * G_LEN + g) * 3;
        bP[d] = xp[0];
        bT[d] = xp[1];
        bE[d] = xp[2];
    }

    for (int t0 = 0; t0 < T_LEN; t0 += DEPTH) {
#pragma unroll
        for (int d = 0; d < DEPTH; d++) {
            const int t = t0 + d;

            // ---- consume slot d (loaded DEPTH steps ago: ready) ----
            const float P  = bP[d];
            const float Tc = bT[d];
            const float E  = bE[d];

            // ---- refill slot d with step t+DEPTH (clamped) ----
            const int tn = (t + DEPTH < T_LEN) ? (t + DEPTH) : (T_LEN - 1);
            const float* xn = x + ((size_t)tn * G_LEN + g) * 3;
            bP[d] = xn[0];
            bT[d] = xn[1];
            bE[d] = xn[2];

            // ---- input-only preprocessing (operands long since ready) ----
            const float rain  = (Tc >= tt) ? P : 0.0f;
            const float snow  = P - rain;
            const float mpot  = fmaxf(cfmax * (Tc - tt), 0.0f);
            const float rfpot = fmaxf(cfrcf * (tt - Tc), 0.0f);
            const float PEl   = E * inv_lpfc;

            // ---- sw from previous sm: MUFU chain starts immediately ----
            // sm/fc in (0,1] (sm>=1e-5, sm<=fc by construction).
            float sw = __powf(sm * inv_fc, beta);
            sw = fminf(sw, 1.0f);
            const float omsw = 1.0f - sw;

            // ---- snow routine (parallel with the MUFU chain) ----
            snowpack += snow;
            const float melt = fminf(mpot, snowpack);
            const float mw1  = meltwater + melt;
            const float refreeze = fminf(rfpot, mw1);
            snowpack = snowpack - melt + refreeze;
            const float mw2 = mw1 - refreeze;
            const float tosoil = fmaxf(mw2 - cwh * snowpack, 0.0f);
            meltwater = mw2 - tosoil;

            // ---- soil routine (critical chain) ----
            const float influx   = rain + tosoil;
            const float recharge = influx * sw;
            const float sm1 = fmaf(influx, omsw, sm);   // sm + influx*(1-sw)
            const float excess = fmaxf(sm1 - fc, 0.0f);
            const float sm2 = fminf(sm1, fc);           // == sm1 - excess
            // etact = min(sm2, E * clip(sm2/(lp*fc),0,1))
            //       = min(min(sm2, E), PEl * sm2)       (E >= 0)
            const float etact = fminf(fminf(sm2, E), PEl * sm2);
            sm = fmaxf(sm2 - etact, 1e-5f);

            // ---- response routine ----
            const float suz1 = suz + recharge + excess;
            const float prc  = fminf(suz1, perc);
            const float suz2 = suz1 - prc;
            const float q0   = k0 * fmaxf(suz2 - uzl, 0.0f);
            const float suz3 = suz2 - q0;
            const float q1   = k1 * suz3;
            suz = suz3 - q1;
            const float slz1 = slz + prc;
            const float q2   = k2 * slz1;
            slz = slz1 - q2;

            // ---- mean over NMUL (4 adjacent lanes); off the state chain ----
            float q = q0 + q1 + q2;
            q += __shfl_xor_sync(0xFFFFFFFFu, q, 1);
            q += __shfl_xor_sync(0xFFFFFFFFu, q, 2);
            if (m == 0)
                g_qs[(size_t)t * G_LEN + g] = q * 0.25f;
        }
    }
}

// ---------------------------------------------------------------------------
// Kernel 2: 15-tap gamma unit hydrograph per grid cell. The normalization by
// w.sum(0) cancels 1/(Gamma(aa)*th^aa) exactly.
// ---------------------------------------------------------------------------
__global__ void __launch_bounds__(128)
weights_kernel(const float* __restrict__ prm)
{
    const int g = blockIdx.x * 128 + threadIdx.x;
    if (g >= G_LEN) return;
    const float* pr = prm + (size_t)g * PRM_STRIDE;
    const float a = pr[NPHY * NMULC + 0] * 2.9f;   // ROUTE_A in [0, 2.9]
    const float b = pr[NPHY * NMULC + 1] * 6.5f;   // ROUTE_B in [0, 6.5]
    const float aa = fmaxf(a, 0.0f) + 0.1f;
    const float th = fmaxf(b, 0.0f) + 0.5f;
    const float inv_th = 1.0f / th;
    const float am1 = aa - 1.0f;

    float u[LENF];
    float s = 0.0f;
#pragma unroll
    for (int l = 0; l < LENF; l++) {
        const float tg = (float)l + 0.5f;
        const float v = powf(tg, am1) * expf(-tg * inv_th);
        u[l] = v;
        s += v;
    }
    const float inv_s = 1.0f / s;
#pragma unroll
    for (int l = 0; l < LENF; l++)
        g_w[l * G_LEN + g] = u[l] * inv_s;
}

// ---------------------------------------------------------------------------
// Kernel 3: 15-tap FIR over qs. 2D grid: blockIdx.y = output time row,
// (blockIdx.x, threadIdx.x) cover g. No div/mod; coalesced along g.
// ---------------------------------------------------------------------------
__global__ void __launch_bounds__(256)
conv_kernel(float* __restrict__ out)
{
    const int g = blockIdx.x * 256 + threadIdx.x;
    if (g >= G_LEN) return;
    const int t = blockIdx.y + WARM;

    float acc = 0.0f;
#pragma unroll
    for (int l = 0; l < LENF; l++)
        acc += g_w[l * G_LEN + g] * g_qs[(size_t)(t - l) * G_LEN + g];

    out[(size_t)blockIdx.y * G_LEN + g] = acc;
}

// ---------------------------------------------------------------------------
extern "C" void kernel_launch(void* const* d_in, const int* in_sizes, int n_in,
                              void* d_out, int out_size)
{
    const float* x_phy = (const float*)d_in[0];   // [2000, 4000, 3]
    const float* prm   = (const float*)d_in[1];   // [1, 4000, 50]
    float* out = (float*)d_out;                   // [1635, 4000, 1]

    const int n_chains = G_LEN * NMULC;           // 16000
    hbv_kernel<<<(n_chains + 127) / 128, 128>>>(x_phy, prm);
    weights_kernel<<<(G_LEN + 127) / 128, 128>>>(prm);
    dim3 cgrid((G_LEN + 255) / 256, T_LEN - WARM);   // (16, 1635)
    conv_kernel<<<cgrid, 256>>>(out);
    (void)in_sizes; (void)n_in; (void)out_size;
}